// round 3
// baseline (speedup 1.0000x reference)
#include <cuda_runtime.h>
#include <cuda_bf16.h>
#include <cstdint>

// Problem constants (fixed by the reference setup)
#define HDIM 64
#define WDIM 64
#define NDIM (HDIM * WDIM)      // 4096
#define ROWCAP 128              // per-row bucket cap (max row count ~45 for Binomial(81920,1/4096))

// ---------------- scratch (device globals; no allocation allowed) ----------------
__device__ float  g_rowsum[NDIM];          // d_k = rowsum of scaled Wcm
__device__ int    g_cnt[NDIM];             // per-row entry count
__device__ int    g_col[NDIM * ROWCAP];    // per-row bucketed cols
__device__ float  g_val[NDIM * ROWCAP];    // per-row bucketed scaled values

// ---------------- kernels ----------------

// Zero the whole output (A then b) with float4 stores; first NDIM threads also
// clear the scratch rowsum/counters (fused to save a launch).
__global__ void k_zero(float4* __restrict__ out, int n4) {
    int i = blockIdx.x * blockDim.x + threadIdx.x;
    if (i < NDIM) { g_rowsum[i] = 0.f; g_cnt[i] = 0; }
    int stride = gridDim.x * blockDim.x;
    float4 z = make_float4(0.f, 0.f, 0.f, 0.f);
    for (; i < n4; i += stride) out[i] = z;
}

// Pass over COO: scale by CM_weights[row], accumulate row sums, bucket entries by row.
__global__ void k_build(const int* __restrict__ rows, const int* __restrict__ cols,
                        const float* __restrict__ data, const float* __restrict__ cmw,
                        int nnz) {
    int e = blockIdx.x * blockDim.x + threadIdx.x;
    if (e >= nnz) return;
    int r = rows[e];
    int c = cols[e];
    float v = data[e] * cmw[r];
    atomicAdd(&g_rowsum[r], v);
    int slot = atomicAdd(&g_cnt[r], 1);
    if (slot < ROWCAP) {
        g_col[r * ROWCAP + slot] = c;
        g_val[r * ROWCAP + slot] = v;
    }
}

// Quadratic term WcmT*Wcm: one warp per row; all ordered pairs of that row's
// entries. Exact even with duplicate (r,c) raw entries: the all-ordered-pairs
// sum over raw values equals the product of composed sums (bilinearity).
__global__ void k_pairs(float* __restrict__ A) {
    int warp_id = (blockIdx.x * blockDim.x + threadIdx.x) >> 5;
    int lane = threadIdx.x & 31;
    if (warp_id >= NDIM) return;

    __shared__ int   s_col[8][ROWCAP];
    __shared__ float s_val[8][ROWCAP];
    int wslot = (threadIdx.x >> 5);

    int cnt = g_cnt[warp_id];
    if (cnt > ROWCAP) cnt = ROWCAP;
    if (cnt == 0) return;

    const int*   gc = g_col + warp_id * ROWCAP;
    const float* gv = g_val + warp_id * ROWCAP;
    for (int t = lane; t < cnt; t += 32) {
        s_col[wslot][t] = gc[t];
        s_val[wslot][t] = gv[t];
    }
    __syncwarp();

    int total = cnt * cnt;
    for (int idx = lane; idx < total; idx += 32) {
        int i = idx / cnt;
        int j = idx - i * cnt;
        float p = s_val[wslot][i] * s_val[wslot][j];
        atomicAdd(&A[s_col[wslot][i] * NDIM + s_col[wslot][j]], p);
    }
}

// Linear terms of Lcm^T Lcm: -(D*Wcm) and -(WcmT*D), per raw COO entry.
// (D W)[r,c] = d_r * W[r,c];  (W^T D)[c,r] = W[r,c] * d_r.
__global__ void k_linear(const int* __restrict__ rows, const int* __restrict__ cols,
                         const float* __restrict__ data, const float* __restrict__ cmw,
                         float* __restrict__ A, int nnz) {
    int e = blockIdx.x * blockDim.x + threadIdx.x;
    if (e >= nnz) return;
    int r = rows[e];
    int c = cols[e];
    float v = data[e] * cmw[r];
    float t = g_rowsum[r] * v;
    atomicAdd(&A[r * NDIM + c], -t);
    atomicAdd(&A[c * NDIM + r], -t);
}

// LOC Laplacian. For sample i, tap j:
//   p = inInd[i] - 1 - W  (the fixed row: neigh[:,0])
//   q = inInd[i] + offs[j],  offs[j] = (j/3 - 1) + (j%3 - 1)*W
//   v = LOC_flows[j,0,i] * LOC_weights[inInd[i]]
// Symmetrized Laplacian of scatter (p,q,v): +v/2 both diagonals, -v/2 both
// off-diagonals (self entries p==q cancel to zero identically).
__global__ void k_loc(const int* __restrict__ inInd, const float* __restrict__ flows,
                      const float* __restrict__ locw, float* __restrict__ A, int m) {
    int t = blockIdx.x * blockDim.x + threadIdx.x;
    if (t >= m * 9) return;
    int i = t / 9;
    int j = t - i * 9;
    int base = inInd[i];
    int off = (j / 3 - 1) + (j % 3 - 1) * WDIM;   // {-1-W,-1,-1+W,-W,0,W,1-W,1,1+W}
    int p = base - 1 - WDIM;
    int q = base + off;
    float v = 0.5f * flows[(size_t)j * 9 * m + i] * locw[base];
    atomicAdd(&A[p * NDIM + p], v);
    atomicAdd(&A[q * NDIM + q], v);
    atomicAdd(&A[p * NDIM + q], -v);
    atomicAdd(&A[q * NDIM + p], -v);
}

// IU Laplacian: per (sample i, tap j<5): r = IU_inInd[i], c = IU_neighInd[i,j],
// v = IU_flows[i,j] * IU_weights[r]; same symmetrized-Laplacian scatter.
__global__ void k_iu(const int* __restrict__ inInd, const float* __restrict__ flows,
                     const int* __restrict__ neigh, const float* __restrict__ iuw,
                     float* __restrict__ A, int m) {
    int t = blockIdx.x * blockDim.x + threadIdx.x;
    if (t >= m * 5) return;
    int i = t / 5;
    int j = t - i * 5;
    int r = inInd[i];
    int c = neigh[i * 5 + j];
    float v = 0.5f * flows[i * 5 + j] * iuw[r];
    atomicAdd(&A[r * NDIM + r], v);
    atomicAdd(&A[c * NDIM + c], v);
    atomicAdd(&A[r * NDIM + c], -v);
    atomicAdd(&A[c * NDIM + r], -v);
}

// Diagonal closure: D^2 from Lcm, ku/known diagonal, and b.
__global__ void k_diag(const float* __restrict__ kuw, const float* __restrict__ kconf,
                       const float* __restrict__ known, const float* __restrict__ kToU,
                       const float* __restrict__ lmbda_p,
                       float* __restrict__ A, float* __restrict__ b) {
    int i = blockIdx.x * blockDim.x + threadIdx.x;
    if (i >= NDIM) return;
    float lam = *lmbda_p;
    float g = kuw[i] * kconf[i] + lam * known[i];
    float d = g_rowsum[i];
    atomicAdd(&A[i * NDIM + i], d * d + g);
    b[i] = g * kToU[i];
}

// ---------------- launch ----------------
extern "C" void kernel_launch(void* const* d_in, const int* in_sizes, int n_in,
                              void* d_out, int out_size) {
    // Robust to whether the scalar height/width inputs are materialized:
    // expected full layout has 18 inputs with CM_weights at index 2. If the
    // harness drops the two leading int scalars, everything shifts by -2.
    int o = (n_in >= 18) ? 2 : (n_in - 16);
    if (o < 0) o = 0;

    const float* CM_weights  = (const float*)d_in[o + 0];
    const float* LOC_weights = (const float*)d_in[o + 1];
    const float* IU_weights  = (const float*)d_in[o + 2];
    const float* KU_weights  = (const float*)d_in[o + 3];
    const float* lmbda       = (const float*)d_in[o + 4];
    const float* kToUconf    = (const float*)d_in[o + 5];
    const float* known       = (const float*)d_in[o + 6];
    const float* kToU        = (const float*)d_in[o + 7];
    const int*   Wcm_row     = (const int*)d_in[o + 8];
    const int*   Wcm_col     = (const int*)d_in[o + 9];
    const float* Wcm_data    = (const float*)d_in[o + 10];
    const int*   LOC_inInd   = (const int*)d_in[o + 11];
    const float* LOC_flows   = (const float*)d_in[o + 12];
    const int*   IU_inInd    = (const int*)d_in[o + 13];
    const float* IU_flows    = (const float*)d_in[o + 14];
    const int*   IU_neighInd = (const int*)d_in[o + 15];

    int nnz   = in_sizes[o + 8];
    int m_loc = in_sizes[o + 11];      // LOC_inInd is (M_LOC, 1)
    int m_iu  = in_sizes[o + 13];      // IU_inInd is (M_IU, 1)

    float* A = (float*)d_out;
    float* b = A + (size_t)NDIM * NDIM;

    // 1. zero output + scratch (fused)
    int n4 = out_size / 4;
    k_zero<<<4096, 256>>>((float4*)d_out, n4);
    // 2. build row buckets + row sums
    k_build<<<(nnz + 255) / 256, 256>>>(Wcm_row, Wcm_col, Wcm_data, CM_weights, nnz);
    // 3. quadratic term (WcmT Wcm): one warp per row
    k_pairs<<<(NDIM * 32 + 255) / 256, 256>>>(A);
    // 4. linear terms (-DW - WTD)
    k_linear<<<(nnz + 255) / 256, 256>>>(Wcm_row, Wcm_col, Wcm_data, CM_weights, A, nnz);
    // 5. LOC Laplacian
    k_loc<<<(m_loc * 9 + 255) / 256, 256>>>(LOC_inInd, LOC_flows, LOC_weights, A, m_loc);
    // 6. IU Laplacian
    k_iu<<<(m_iu * 5 + 255) / 256, 256>>>(IU_inInd, IU_flows, IU_neighInd, IU_weights, A, m_iu);
    // 7. diagonal + b
    k_diag<<<(NDIM + 255) / 256, 256>>>(KU_weights, kToUconf, known, kToU, lmbda, A, b);
}